// round 16
// baseline (speedup 1.0000x reference)
#include <cuda_runtime.h>

// Two-kernel fused spiking conv2d (T=128, Cin=16, Cout=64, 64x64, pad=1) + LIF.
// K1: conv+bias, PERSISTENT blocks (288 = 2/SM). Each block owns one
//     (row-band, cout-group-of-16) combo and a ~14-timestep chunk:
//     weights staged once, x[t+1] prefetched into a second smem buffer via
//     cp.async while t computes -> staging off the critical path, one
//     barrier per t, no launch-grid tail. Body identical to R15:
//     f32x2 lanes = cout-pairs, non-duplicated weights, x dup via ALU MOV.
// K2: in-place LIF scan (MLP=8) -- at its RMW floor (~41us).
// Bit-exact: per-output (cin,kh,kw) fma2 chain + (conv+b) then (state+conv).

#define T_STEPS 128
#define CIN     16
#define HH      64
#define WWID    64
#define COUT    64

#define BAND    8               // output rows per block
#define ROWS_S  10              // band + top/bottom halo rows
#define COLS_P  72              // 4 left-pad + 64 + 4 right-pad
#define XOFF    4               // column c stored at [XOFF + c]
#define NROWS   (CIN * ROWS_S)  // 160 staged rows
#define XS_FLOATS (NROWS * COLS_P)   // 11520 floats = 46080 B per buffer
#define NCOMBO  32              // 8 bands x 4 cout-groups
#define NCHUNK  9               // t-chunks per combo
#define NBLOCKS (NCOMBO * NCHUNK)    // 288 = 2 per SM on 144 SMs

typedef unsigned long long ull;

__device__ __forceinline__ void fma2(ull& d, ull a, ull b) {
    asm("fma.rn.f32x2 %0, %1, %2, %0;" : "+l"(d) : "l"(a), "l"(b));
}
__device__ __forceinline__ ull dup2(float v) {
    ull r;
    asm("mov.b64 %0, {%1, %1};" : "=l"(r) : "f"(v));
    return r;
}
__device__ __forceinline__ void unpack2(ull v, float& lo, float& hi) {
    asm("mov.b64 {%0, %1}, %2;" : "=f"(lo), "=f"(hi) : "l"(v));
}
__device__ __forceinline__ float fadd(float a, float b) {
    float r;
    asm("add.rn.f32 %0, %1, %2;" : "=f"(r) : "f"(a), "f"(b));
    return r;
}
__device__ __forceinline__ void cp16(unsigned saddr, const void* g) {
    asm volatile("cp.async.cg.shared.global [%0], [%1], 16;"
                 :: "r"(saddr), "l"(g));
}
__device__ __forceinline__ void cp_commit() {
    asm volatile("cp.async.commit_group;");
}
__device__ __forceinline__ void cp_wait_all() {
    asm volatile("cp.async.wait_group 0;");
}

// Stage the valid 16B chunks of x[t] into buffer at sbase (invalid halo rows
// stay zero from the one-time buffer clear).
__device__ __forceinline__ void stage_x(unsigned sbase, const float* xsrc,
                                        int tid, int ht)
{
    #pragma unroll
    for (int j = 0; j < 10; ++j) {
        int k     = tid + 256 * j;        // 2560 chunks total
        int rowid = k >> 4;
        int kk    = k & 15;
        int cin   = rowid / ROWS_S;
        int rr    = rowid - cin * ROWS_S;
        int gh    = ht - 1 + rr;
        if (gh >= 0 && gh < HH)
            cp16(sbase + (unsigned)((rowid * COLS_P + XOFF + kk * 4) * 4),
                 xsrc + cin * (HH * WWID) + gh * WWID + kk * 4);
    }
}

// ---------------- K1: conv + bias (persistent, double-buffered) -------------
__global__ __launch_bounds__(256, 2)
void conv_kernel(const float* __restrict__ x,
                 const float* __restrict__ Wg,
                 const float* __restrict__ bg,
                 float* __restrict__ out)
{
    extern __shared__ float xs[];                 // 2 x XS_FLOATS
    __shared__ float ws[CIN][9][16];              // weights, 16 couts, no dup

    const int tid   = threadIdx.x;
    const int cg    = tid >> 7;          // 0/1 : cout half
    const int rt    = tid & 127;
    const int ty    = rt >> 4;           // 0..7  : row within band
    const int tx    = rt & 15;           // 0..15 : w-quad
    const int combo = blockIdx.x & (NCOMBO - 1);
    const int chunk = blockIdx.x >> 5;   // 0..8
    const int band  = combo & 7;
    const int cy    = combo >> 3;        // cout group of 16
    const int ht    = band * BAND;
    const int c0    = (cy << 4) + (cg << 3);
    const int tbeg  = (chunk * T_STEPS) / NCHUNK;
    const int tend  = ((chunk + 1) * T_STEPS) / NCHUNK;

    const int h0 = ht + ty;
    const int w0 = tx * 4;

    unsigned xs_u32;
    {
        unsigned long long tmp = __cvta_generic_to_shared(xs);
        xs_u32 = (unsigned)tmp;
    }

    // ---- one-time: zero BOTH buffers (halos stay zero forever) ----
    {
        float4* z = reinterpret_cast<float4*>(xs);
        for (int i = tid; i < 2 * XS_FLOATS / 4; i += 256)
            z[i] = make_float4(0.f, 0.f, 0.f, 0.f);
    }

    // ---- one-time: weights, coalesced float4 load + smem scatter ----
    {
        const float4* wsrc = reinterpret_cast<const float4*>(
            Wg + (size_t)(cy << 4) * (CIN * 9));   // 2304 floats contiguous
        for (int i4 = tid; i4 < 576; i4 += 256) {
            float4 wv = __ldg(wsrc + i4);
            int flat = i4 * 4;
            #pragma unroll
            for (int u = 0; u < 4; ++u) {
                int idx = flat + u;
                int c   = idx / 144;
                int rem = idx - c * 144;
                int cin = rem / 9;
                int tap = rem - cin * 9;
                ws[cin][tap][c] = (&wv.x)[u];
            }
        }
    }
    __syncthreads();   // zeros visible before cp.async writes land among them

    // ---- prologue: stage x[tbeg] into buffer 0 ----
    stage_x(xs_u32, x + (size_t)tbeg * (CIN * HH * WWID), tid, ht);
    cp_commit();
    cp_wait_all();
    __syncthreads();

    const int cg8 = cg << 3;

    #pragma unroll 1
    for (int t = tbeg; t < tend; ++t) {
        const int cur = (t - tbeg) & 1;

        // prefetch x[t+1] into the other buffer (overlaps compute below)
        if (t + 1 < tend) {
            stage_x(xs_u32 + (unsigned)((cur ^ 1) * (XS_FLOATS * 4)),
                    x + (size_t)(t + 1) * (CIN * HH * WWID), tid, ht);
            cp_commit();
        }

        const float* xb = xs + cur * XS_FLOATS;

        ull acc[4][4];
        #pragma unroll
        for (int cp = 0; cp < 4; ++cp)
            #pragma unroll
            for (int p = 0; p < 4; ++p) acc[cp][p] = 0ull;

        #pragma unroll 4
        for (int cin = 0; cin < CIN; ++cin) {
            #pragma unroll
            for (int r = 0; r < 3; ++r) {
                const float* rowp = xb + (cin * ROWS_S + ty + r) * COLS_P + XOFF + w0;
                float4 xq = *reinterpret_cast<const float4*>(rowp);   // x0..x3
                float  xm = rowp[-1];                                 // x-1
                float  xp = rowp[4];                                  // x4

                ull xd0 = dup2(xm);
                ull xd1 = dup2(xq.x);
                ull xd2 = dup2(xq.y);
                ull xd3 = dup2(xq.z);
                ull xd4 = dup2(xq.w);
                ull xd5 = dup2(xp);

                const ulonglong2* w0v =
                    reinterpret_cast<const ulonglong2*>(&ws[cin][r * 3 + 0][cg8]);
                const ulonglong2* w1v =
                    reinterpret_cast<const ulonglong2*>(&ws[cin][r * 3 + 1][cg8]);
                const ulonglong2* w2v =
                    reinterpret_cast<const ulonglong2*>(&ws[cin][r * 3 + 2][cg8]);
                ulonglong2 Wk0a = w0v[0], Wk0b = w0v[1];
                ulonglong2 Wk1a = w1v[0], Wk1b = w1v[1];
                ulonglong2 Wk2a = w2v[0], Wk2b = w2v[1];

                // per-accumulator order: kw0, kw1, kw2 (bit-exact chain)
                fma2(acc[0][0], xd0, Wk0a.x); fma2(acc[0][0], xd1, Wk1a.x); fma2(acc[0][0], xd2, Wk2a.x);
                fma2(acc[0][1], xd1, Wk0a.x); fma2(acc[0][1], xd2, Wk1a.x); fma2(acc[0][1], xd3, Wk2a.x);
                fma2(acc[0][2], xd2, Wk0a.x); fma2(acc[0][2], xd3, Wk1a.x); fma2(acc[0][2], xd4, Wk2a.x);
                fma2(acc[0][3], xd3, Wk0a.x); fma2(acc[0][3], xd4, Wk1a.x); fma2(acc[0][3], xd5, Wk2a.x);

                fma2(acc[1][0], xd0, Wk0a.y); fma2(acc[1][0], xd1, Wk1a.y); fma2(acc[1][0], xd2, Wk2a.y);
                fma2(acc[1][1], xd1, Wk0a.y); fma2(acc[1][1], xd2, Wk1a.y); fma2(acc[1][1], xd3, Wk2a.y);
                fma2(acc[1][2], xd2, Wk0a.y); fma2(acc[1][2], xd3, Wk1a.y); fma2(acc[1][2], xd4, Wk2a.y);
                fma2(acc[1][3], xd3, Wk0a.y); fma2(acc[1][3], xd4, Wk1a.y); fma2(acc[1][3], xd5, Wk2a.y);

                fma2(acc[2][0], xd0, Wk0b.x); fma2(acc[2][0], xd1, Wk1b.x); fma2(acc[2][0], xd2, Wk2b.x);
                fma2(acc[2][1], xd1, Wk0b.x); fma2(acc[2][1], xd2, Wk1b.x); fma2(acc[2][1], xd3, Wk2b.x);
                fma2(acc[2][2], xd2, Wk0b.x); fma2(acc[2][2], xd3, Wk1b.x); fma2(acc[2][2], xd4, Wk2b.x);
                fma2(acc[2][3], xd3, Wk0b.x); fma2(acc[2][3], xd4, Wk1b.x); fma2(acc[2][3], xd5, Wk2b.x);

                fma2(acc[3][0], xd0, Wk0b.y); fma2(acc[3][0], xd1, Wk1b.y); fma2(acc[3][0], xd2, Wk2b.y);
                fma2(acc[3][1], xd1, Wk0b.y); fma2(acc[3][1], xd2, Wk1b.y); fma2(acc[3][1], xd3, Wk2b.y);
                fma2(acc[3][2], xd2, Wk0b.y); fma2(acc[3][2], xd3, Wk1b.y); fma2(acc[3][2], xd4, Wk2b.y);
                fma2(acc[3][3], xd3, Wk0b.y); fma2(acc[3][3], xd4, Wk1b.y); fma2(acc[3][3], xd5, Wk2b.y);
            }
        }

        // ---- write rounded conv_t + b as float4 per cout ----
        float* o = out + (size_t)t * (COUT * HH * WWID)
                       + (size_t)c0 * (HH * WWID) + h0 * WWID + w0;
        #pragma unroll
        for (int cp = 0; cp < 4; ++cp) {
            float lo0, hi0, lo1, hi1, lo2, hi2, lo3, hi3;
            unpack2(acc[cp][0], lo0, hi0);
            unpack2(acc[cp][1], lo1, hi1);
            unpack2(acc[cp][2], lo2, hi2);
            unpack2(acc[cp][3], lo3, hi3);
            const float be = bg[c0 + 2 * cp];
            const float bo = bg[c0 + 2 * cp + 1];
            *reinterpret_cast<float4*>(o + (size_t)(2 * cp) * (HH * WWID)) =
                make_float4(fadd(lo0, be), fadd(lo1, be), fadd(lo2, be), fadd(lo3, be));
            *reinterpret_cast<float4*>(o + (size_t)(2 * cp + 1) * (HH * WWID)) =
                make_float4(fadd(hi0, bo), fadd(hi1, bo), fadd(hi2, bo), fadd(hi3, bo));
        }

        // prefetch must be complete and all readers done before next overwrite
        cp_wait_all();
        __syncthreads();
    }
}

// ---------------- K2: in-place LIF scan over t (float4, MLP=8) --------------
__global__ __launch_bounds__(64)
void scan_kernel(float* __restrict__ out)
{
    const int idx = blockIdx.x * 64 + threadIdx.x;   // float4 element index
    float4* p = reinterpret_cast<float4*>(out) + idx;
    const int stride4 = (COUT * HH * WWID) / 4;

    float4 s = make_float4(0.f, 0.f, 0.f, 0.f);
    #pragma unroll 1
    for (int tb = 0; tb < T_STEPS; tb += 8) {
        float4 c[8];
        #pragma unroll
        for (int u = 0; u < 8; ++u)
            c[u] = __ldcs(p + (size_t)(tb + u) * stride4);
        #pragma unroll
        for (int u = 0; u < 8; ++u) {
            float4 v;
            v.x = fadd(s.x, c[u].x); v.y = fadd(s.y, c[u].y);
            v.z = fadd(s.z, c[u].z); v.w = fadd(s.w, c[u].w);
            float4 k;
            k.x = (v.x >= 8.f) ? 1.f : 0.f;  k.y = (v.y >= 8.f) ? 1.f : 0.f;
            k.z = (v.z >= 8.f) ? 1.f : 0.f;  k.w = (v.w >= 8.f) ? 1.f : 0.f;
            v.x = (v.x >= 8.f) ? 0.f : v.x;  v.y = (v.y >= 8.f) ? 0.f : v.y;
            v.z = (v.z >= 8.f) ? 0.f : v.z;  v.w = (v.w >= 8.f) ? 0.f : v.w;
            s.x = fmaxf(v.x, -1.f);          s.y = fmaxf(v.y, -1.f);
            s.z = fmaxf(v.z, -1.f);          s.w = fmaxf(v.w, -1.f);
            __stcs(p + (size_t)(tb + u) * stride4, k);
        }
    }
}

extern "C" void kernel_launch(void* const* d_in, const int* in_sizes, int n_in,
                              void* d_out, int out_size)
{
    const float* x  = (const float*)d_in[0];   // [128,16,64,64]
    const float* Wg = (const float*)d_in[1];   // [64,16,3,3]
    const float* bg = (const float*)d_in[2];   // [64]
    float* out      = (float*)d_out;           // [128,64,64,64]

    static int attr_set = 0;
    size_t xs_bytes = (size_t)2 * XS_FLOATS * sizeof(float);   // 92160 B
    if (!attr_set) {
        cudaFuncSetAttribute(conv_kernel,
                             cudaFuncAttributeMaxDynamicSharedMemorySize,
                             (int)xs_bytes);
        attr_set = 1;
    }

    conv_kernel<<<NBLOCKS, 256, xs_bytes>>>(x, Wg, bg, out);

    scan_kernel<<<(COUT * HH * WWID) / 4 / 64, 64>>>(out);
}